// round 10
// baseline (speedup 1.0000x reference)
#include <cuda_runtime.h>
#include <cuda_fp16.h>
#include <math.h>
#include <cstdint>

#define DIM   512
#define NTOK  8192
#define HDIM  64
#define SEQ   2048
#define QKV_N 1536
// SCALE * log2(e): Q prescaled so softmax is a bare ex2
#define QS_LOG2E 0.18033688011112042f

// ---------------- scratch ----------------
__device__ __align__(256) __half g_q [NTOK * DIM];   // [bh][n][64], pre-scaled
__device__ __align__(256) __half g_k [NTOK * DIM];
__device__ __align__(256) __half g_v [NTOK * DIM];
__device__ __align__(256) __half g_o [NTOK * DIM];   // [t][512]
__device__ __align__(256) __half g_wq[QKV_N * DIM];  // qkv_w * ln_w (fp16)
__device__ __align__(256) __half g_wo[DIM * DIM];
__device__ __align__(256) float2 g_st[NTOK];         // (mu, rinv) per token
__device__ __align__(256) float  g_qb2[QKV_N];       // qkv_b + qkv_w @ ln_b

// ---------------- PTX helpers ----------------
__device__ __forceinline__ uint32_t smem_u32(const void* p) {
    uint32_t a;
    asm("{ .reg .u64 t; cvta.to.shared.u64 t, %1; cvt.u32.u64 %0, t; }" : "=r"(a) : "l"(p));
    return a;
}
#define CP_ASYNC16(dst, src) \
    asm volatile("cp.async.cg.shared.global [%0], [%1], 16;" :: "r"(dst), "l"(src))
#define CP_COMMIT() asm volatile("cp.async.commit_group;" ::: "memory")
#define CP_WAIT(n)  asm volatile("cp.async.wait_group %0;" :: "n"(n) : "memory")

__device__ __forceinline__ void ldsm4(uint32_t* r, uint32_t a) {
    asm volatile("ldmatrix.sync.aligned.m8n8.x4.shared.b16 {%0,%1,%2,%3}, [%4];"
                 : "=r"(r[0]), "=r"(r[1]), "=r"(r[2]), "=r"(r[3]) : "r"(a));
}
__device__ __forceinline__ void ldsm4t(uint32_t* r, uint32_t a) {
    asm volatile("ldmatrix.sync.aligned.m8n8.x4.trans.shared.b16 {%0,%1,%2,%3}, [%4];"
                 : "=r"(r[0]), "=r"(r[1]), "=r"(r[2]), "=r"(r[3]) : "r"(a));
}
__device__ __forceinline__ void mma16(float* d, const uint32_t* a, const uint32_t* b) {
    asm volatile(
        "mma.sync.aligned.m16n8k16.row.col.f32.f16.f16.f32 "
        "{%0,%1,%2,%3}, {%4,%5,%6,%7}, {%8,%9}, {%0,%1,%2,%3};"
        : "+f"(d[0]), "+f"(d[1]), "+f"(d[2]), "+f"(d[3])
        : "r"(a[0]), "r"(a[1]), "r"(a[2]), "r"(a[3]), "r"(b[0]), "r"(b[1]));
}
__device__ __forceinline__ uint32_t packh2(float lo, float hi) {
    __half2 h = __floats2half2_rn(lo, hi);
    return *reinterpret_cast<uint32_t*>(&h);
}
__device__ __forceinline__ float ex2(float x) {
    float r;
    asm("ex2.approx.f32 %0, %1;" : "=f"(r) : "f"(x));
    return r;
}
// 128B-row XOR swizzle on 16B units
__device__ __forceinline__ uint32_t swz(uint32_t row, uint32_t c16) {
    return row * 128 + ((c16 ^ (row & 7)) * 16);
}

// -------- prep: LN stats per token --------
__global__ __launch_bounds__(256) void ln_stats(const float* __restrict__ x)
{
    int row = blockIdx.x, t = threadIdx.x;
    float2 v = ((const float2*)(x + (size_t)row * DIM))[t];
    float s = v.x + v.y, ss = v.x * v.x + v.y * v.y;
    #pragma unroll
    for (int off = 16; off > 0; off >>= 1) {
        s  += __shfl_xor_sync(0xffffffffu, s,  off);
        ss += __shfl_xor_sync(0xffffffffu, ss, off);
    }
    __shared__ float rs[8], rss[8];
    int wid = t >> 5, lane = t & 31;
    if (lane == 0) { rs[wid] = s; rss[wid] = ss; }
    __syncthreads();
    if (t == 0) {
        float S = 0.f, SS = 0.f;
        #pragma unroll
        for (int i = 0; i < 8; i++) { S += rs[i]; SS += rss[i]; }
        float mu = S * (1.0f / DIM);
        float var = SS * (1.0f / DIM) - mu * mu;
        g_st[row] = make_float2(mu, rsqrtf(var + 1e-5f));
    }
}

// -------- prep: weights fp32->fp16 (qkv gets ln_w folded in) --------
#define WQ_BLOCKS (QKV_N * DIM / 1024)     // 768
#define WO_BLOCKS (DIM * DIM / 1024)       // 256
__global__ __launch_bounds__(256) void cvt_w(
    const float* __restrict__ qkv_w, const float* __restrict__ out_w,
    const float* __restrict__ ln_w)
{
    int blk = blockIdx.x;
    if (blk < WQ_BLOCKS) {
        int i = blk * 256 + threadIdx.x;               // float4 index
        float4 v = ((const float4*)qkv_w)[i];
        float4 w = ((const float4*)ln_w)[i & 127];     // col = (i*4) % 512
        ((uint32_t*)g_wq)[i * 2 + 0] = packh2(v.x * w.x, v.y * w.y);
        ((uint32_t*)g_wq)[i * 2 + 1] = packh2(v.z * w.z, v.w * w.w);
    } else {
        int i = (blk - WQ_BLOCKS) * 256 + threadIdx.x;
        float4 v = ((const float4*)out_w)[i];
        ((uint32_t*)g_wo)[i * 2 + 0] = packh2(v.x, v.y);
        ((uint32_t*)g_wo)[i * 2 + 1] = packh2(v.z, v.w);
    }
}

// -------- prep: bias2 = qkv_b + qkv_w @ ln_b --------
__global__ __launch_bounds__(256) void fold_bias(
    const float* __restrict__ qkv_w, const float* __restrict__ qkv_b,
    const float* __restrict__ ln_b)
{
    int n = blockIdx.x * 256 + threadIdx.x;            // 0..1535
    float s = 0.f;
    const float4* wr = (const float4*)(qkv_w + (size_t)n * DIM);
    const float4* lb = (const float4*)ln_b;
    #pragma unroll 4
    for (int i = 0; i < DIM / 4; i++) {
        float4 w = __ldg(wr + i), b = __ldg(lb + i);
        s += w.x * b.x + w.y * b.y + w.z * b.z + w.w * b.w;
    }
    g_qb2[n] = qkv_b[n] + s;
}

// ======== fp16 GEMM-NT (R8 inner loop): 128x128 tile, 8 warps 64x32 ========
// MODE 0: A = raw fp32 x, normalized in the loader (LDG+STS); B = g_wq.
// MODE 1: A = g_o fp16 via cp.async; B = g_wo.
#define GEMM_SMEM (3 * 32768)

template <int MODE>
__global__ __launch_bounds__(256, 2) void gemm_tc(
    const float* __restrict__ Xsrc,
    const __half* __restrict__ Bmat, const float* __restrict__ bias,
    float* __restrict__ Cout, int N, int K)
{
    extern __shared__ char smraw[];
    const uint32_t sb = smem_u32(smraw);
    const int tid = threadIdx.x, lane = tid & 31, wid = tid >> 5;
    const int wm = wid >> 2, wn = wid & 3;
    const int bm = blockIdx.y * 128, bn = blockIdx.x * 128;

    const int lrow = tid >> 1, half = tid & 1, lc16 = half * 4;
    const __half* Bg = Bmat + (size_t)(bn + lrow) * K + lc16 * 8;

    // MODE 0: fp32 x row pointer + per-row LN stats
    const float4* Xp = nullptr;
    float mu = 0.f, ri = 0.f;
    // MODE 1: fp16 A row pointer
    const __half* Ag = nullptr;
    if (MODE == 0) {
        Xp = (const float4*)(Xsrc + (size_t)(bm + lrow) * DIM) + half * 8;
        float2 st = __ldg((const float2*)g_st + (bm + lrow));
        mu = st.x; ri = st.y;
    } else {
        Ag = g_o + (size_t)(bm + lrow) * K + lc16 * 8;
    }

    float acc[4][4][4];
    #pragma unroll
    for (int i = 0; i < 4; i++)
        #pragma unroll
        for (int j = 0; j < 4; j++)
            { acc[i][j][0]=0.f; acc[i][j][1]=0.f; acc[i][j][2]=0.f; acc[i][j][3]=0.f; }

    const int NC = K / 64;
    // preload chunks 0,1
    #pragma unroll
    for (int c = 0; c < 2; c++) {
        uint32_t base = sb + c * 32768;
        if (MODE == 0) {
            #pragma unroll
            for (int i = 0; i < 4; i++) {
                float4 a = __ldg(Xp + c * 16 + i * 2);
                float4 b = __ldg(Xp + c * 16 + i * 2 + 1);
                uint4 u = make_uint4(packh2((a.x - mu) * ri, (a.y - mu) * ri),
                                     packh2((a.z - mu) * ri, (a.w - mu) * ri),
                                     packh2((b.x - mu) * ri, (b.y - mu) * ri),
                                     packh2((b.z - mu) * ri, (b.w - mu) * ri));
                *(uint4*)(smraw + c * 32768 + swz(lrow, lc16 + i)) = u;
            }
        } else {
            #pragma unroll
            for (int i = 0; i < 4; i++)
                CP_ASYNC16(base + swz(lrow, lc16 + i), (const char*)(Ag + c * 64 + i * 8));
        }
        #pragma unroll
        for (int i = 0; i < 4; i++)
            CP_ASYNC16(base + 16384 + swz(lrow, lc16 + i), (const char*)(Bg + c * 64 + i * 8));
        CP_COMMIT();
    }

    const int arow = wm * 64 + (lane & 15);
    const int brow = wn * 32 + (lane & 7);
    const int acol = lane >> 4;
    const int bcol = lane >> 3;

    for (int c = 0; c < NC; c++) {
        // MODE 0: LDG+convert chunk c+2 before the wait (latency overlap)
        uint4 stg[4];
        if (MODE == 0 && c + 2 < NC) {
            #pragma unroll
            for (int i = 0; i < 4; i++) {
                float4 a = __ldg(Xp + (c + 2) * 16 + i * 2);
                float4 b = __ldg(Xp + (c + 2) * 16 + i * 2 + 1);
                stg[i] = make_uint4(packh2((a.x - mu) * ri, (a.y - mu) * ri),
                                    packh2((a.z - mu) * ri, (a.w - mu) * ri),
                                    packh2((b.x - mu) * ri, (b.y - mu) * ri),
                                    packh2((b.z - mu) * ri, (b.w - mu) * ri));
            }
        }
        if (c + 1 < NC) { CP_WAIT(1); } else { CP_WAIT(0); }
        __syncthreads();
        if (c + 2 < NC) {
            uint32_t base = sb + ((c + 2) % 3) * 32768;
            if (MODE == 0) {
                #pragma unroll
                for (int i = 0; i < 4; i++)
                    *(uint4*)(smraw + ((c + 2) % 3) * 32768 + swz(lrow, lc16 + i)) = stg[i];
            } else {
                #pragma unroll
                for (int i = 0; i < 4; i++)
                    CP_ASYNC16(base + swz(lrow, lc16 + i),
                               (const char*)(Ag + (c + 2) * 64 + i * 8));
            }
            #pragma unroll
            for (int i = 0; i < 4; i++)
                CP_ASYNC16(base + 16384 + swz(lrow, lc16 + i),
                           (const char*)(Bg + (c + 2) * 64 + i * 8));
            CP_COMMIT();
        }

        const uint32_t Ab = sb + (c % 3) * 32768;
        const uint32_t Bb = Ab + 16384;

        uint32_t afA[4][4], afB[4][4], bf[4][4];
        #pragma unroll
        for (int mt = 0; mt < 4; mt++)
            ldsm4(afA[mt], Ab + swz(arow + mt * 16, 0 + acol));
        #pragma unroll
        for (int nt = 0; nt < 4; nt++)
            ldsm4(bf[nt],  Bb + swz(brow + nt * 8,  0 + bcol));
        #pragma unroll
        for (int mt = 0; mt < 4; mt++)
            ldsm4(afB[mt], Ab + swz(arow + mt * 16, 2 + acol));

        #pragma unroll
        for (int mt = 0; mt < 4; mt++)
            #pragma unroll
            for (int nt = 0; nt < 4; nt++)
                mma16(acc[mt][nt], afA[mt], &bf[nt][0]);
        #pragma unroll
        for (int mt = 0; mt < 4; mt++)
            ldsm4(afA[mt], Ab + swz(arow + mt * 16, 4 + acol));
        #pragma unroll
        for (int mt = 0; mt < 4; mt++)
            #pragma unroll
            for (int nt = 0; nt < 4; nt++)
                mma16(acc[mt][nt], afB[mt], &bf[nt][2]);
        #pragma unroll
        for (int nt = 0; nt < 4; nt++)
            ldsm4(bf[nt],  Bb + swz(brow + nt * 8,  4 + bcol));
        #pragma unroll
        for (int mt = 0; mt < 4; mt++)
            ldsm4(afB[mt], Ab + swz(arow + mt * 16, 6 + acol));
        #pragma unroll
        for (int mt = 0; mt < 4; mt++)
            #pragma unroll
            for (int nt = 0; nt < 4; nt++)
                mma16(acc[mt][nt], afA[mt], &bf[nt][0]);
        #pragma unroll
        for (int mt = 0; mt < 4; mt++)
            #pragma unroll
            for (int nt = 0; nt < 4; nt++)
                mma16(acc[mt][nt], afB[mt], &bf[nt][2]);
    }

    #pragma unroll
    for (int mt = 0; mt < 4; mt++) {
        #pragma unroll
        for (int nt = 0; nt < 4; nt++) {
            int m = bm + wm * 64 + mt * 16 + (lane >> 2);
            int n = bn + wn * 32 + nt * 8 + 2 * (lane & 3);
            float2 bb = *(const float2*)(bias + n);
            float lx = acc[mt][nt][0] + bb.x, ly = acc[mt][nt][1] + bb.y;
            float hx = acc[mt][nt][2] + bb.x, hy = acc[mt][nt][3] + bb.y;
            if (MODE == 0) {
                int which = n >> 9, h = (n >> 6) & 7, d = n & 63;
                if (which == 0) {    // pre-scale Q by SCALE*log2(e)
                    lx *= QS_LOG2E; ly *= QS_LOG2E; hx *= QS_LOG2E; hy *= QS_LOG2E;
                }
                __half* dstp = (which == 0) ? g_q : ((which == 1) ? g_k : g_v);
                int bidx = m >> 11, nn = m & 2047;
                size_t base = (size_t)((bidx << 3) + h) * SEQ;
                *(uint32_t*)&dstp[(base + nn)     * HDIM + d] = packh2(lx, ly);
                *(uint32_t*)&dstp[(base + nn + 8) * HDIM + d] = packh2(hx, hy);
            } else {
                *(float2*)&Cout[(size_t)m * N + n]       = make_float2(lx, ly);
                *(float2*)&Cout[(size_t)(m + 8) * N + n] = make_float2(hx, hy);
            }
        }
    }
}

// ======== Attention (byte-identical R8 win) ================================
#define ATTN_SMEM (16384 + 2 * 32768)

__global__ __launch_bounds__(256, 2) void attn_tc()
{
    extern __shared__ char smraw[];
    const uint32_t sb = smem_u32(smraw);
    const int tid = threadIdx.x, lane = tid & 31, wid = tid >> 5;
    const int bh = blockIdx.y, b = bh >> 3, h = bh & 7;
    const int q0 = blockIdx.x * 128;

    const __half* qg = g_q + (size_t)bh * SEQ * HDIM;
    const __half* kg = g_k + (size_t)bh * SEQ * HDIM;
    const __half* vg = g_v + (size_t)bh * SEQ * HDIM;

    const int lrow = tid >> 1, lc16 = (tid & 1) * 4;

    {
        const __half* src = qg + (size_t)(q0 + lrow) * HDIM + lc16 * 8;
        #pragma unroll
        for (int i = 0; i < 4; i++)
            CP_ASYNC16(sb + swz(lrow, lc16 + i), (const char*)(src + i * 8));
        CP_COMMIT();
        const __half* ks = kg + (size_t)lrow * HDIM + lc16 * 8;
        const __half* vs = vg + (size_t)lrow * HDIM + lc16 * 8;
        #pragma unroll
        for (int i = 0; i < 4; i++) {
            CP_ASYNC16(sb + 16384 + swz(lrow, lc16 + i), (const char*)(ks + i * 8));
            CP_ASYNC16(sb + 32768 + swz(lrow, lc16 + i), (const char*)(vs + i * 8));
        }
        CP_COMMIT();
    }

    CP_WAIT(1);
    __syncthreads();
    uint32_t qa[4][4];
    #pragma unroll
    for (int s = 0; s < 4; s++)
        ldsm4(qa[s], sb + swz(wid * 16 + (lane & 15), (s << 1) + (lane >> 4)));

    float o[8][4];
    #pragma unroll
    for (int i = 0; i < 8; i++)
        { o[i][0]=0.f; o[i][1]=0.f; o[i][2]=0.f; o[i][3]=0.f; }
    float la[4] = {0.f, 0.f, 0.f, 0.f};
    const uint32_t ones2[2] = {0x3C003C00u, 0x3C003C00u};

    const int krow7  = lane & 7;
    const int kcol   = lane >> 3;
    const int vrow15 = lane & 15;
    const int vcol   = lane >> 4;

    const int NT = SEQ / 128;
    for (int t = 0; t < NT; t++) {
        CP_WAIT(0);
        __syncthreads();
        if (t + 1 < NT) {
            uint32_t base = sb + 16384 + ((t + 1) & 1) * 32768;
            const __half* ks = kg + (size_t)((t + 1) * 128 + lrow) * HDIM + lc16 * 8;
            const __half* vs = vg + (size_t)((t + 1) * 128 + lrow) * HDIM + lc16 * 8;
            #pragma unroll
            for (int i = 0; i < 4; i++) {
                CP_ASYNC16(base + swz(lrow, lc16 + i),         (const char*)(ks + i * 8));
                CP_ASYNC16(base + 16384 + swz(lrow, lc16 + i), (const char*)(vs + i * 8));
            }
            CP_COMMIT();
        }

        const uint32_t Kb = sb + 16384 + (t & 1) * 32768;
        const uint32_t Vb = Kb + 16384;

        uint32_t kb[2][16];
        ldsm4(kb[0] + 0,  Kb + swz(krow7,     0 + kcol));
        ldsm4(kb[0] + 4,  Kb + swz(krow7,     4 + kcol));
        ldsm4(kb[0] + 8,  Kb + swz(8 + krow7, 0 + kcol));
        ldsm4(kb[0] + 12, Kb + swz(8 + krow7, 4 + kcol));

        #pragma unroll
        for (int g = 0; g < 8; g++) {
            const int kr = g * 16;
            uint32_t* cur = kb[g & 1];
            uint32_t vb[4][4];
            #pragma unroll
            for (int dtp = 0; dtp < 4; dtp++)
                ldsm4t(vb[dtp], Vb + swz(kr + vrow15, 2 * dtp + vcol));
            float sc0[4] = {0.f,0.f,0.f,0.f}, sc1[4] = {0.f,0.f,0.f,0.f};
            mma16(sc0, qa[0], cur + 0);  mma16(sc0, qa[1], cur + 2);
            mma16(sc0, qa[2], cur + 4);  mma16(sc0, qa[3], cur + 6);
            mma16(sc1, qa[0], cur + 8);  mma16(sc1, qa[1], cur + 10);
            mma16(sc1, qa[2], cur + 12); mma16(sc1, qa[3], cur + 14);
            if (g < 7) {
                uint32_t* nxt = kb[(g + 1) & 1];
                ldsm4(nxt + 0,  Kb + swz(kr + 16 + krow7, 0 + kcol));
                ldsm4(nxt + 4,  Kb + swz(kr + 16 + krow7, 4 + kcol));
                ldsm4(nxt + 8,  Kb + swz(kr + 24 + krow7, 0 + kcol));
                ldsm4(nxt + 12, Kb + swz(kr + 24 + krow7, 4 + kcol));
            }
            sc0[0] = ex2(sc0[0]); sc0[1] = ex2(sc0[1]);
            sc0[2] = ex2(sc0[2]); sc0[3] = ex2(sc0[3]);
            sc1[0] = ex2(sc1[0]); sc1[1] = ex2(sc1[1]);
            sc1[2] = ex2(sc1[2]); sc1[3] = ex2(sc1[3]);
            uint32_t pa[4];
            pa[0] = packh2(sc0[0], sc0[1]);
            pa[1] = packh2(sc0[2], sc0[3]);
            pa[2] = packh2(sc1[0], sc1[1]);
            pa[3] = packh2(sc1[2], sc1[3]);
            mma16(la, pa, ones2);
            #pragma unroll
            for (int dtp = 0; dtp < 4; dtp++) {
                mma16(o[2*dtp],     pa, vb[dtp]);
                mma16(o[2*dtp + 1], pa, vb[dtp] + 2);
            }
        }
    }

    float rlo = 1.0f / la[0], rhi = 1.0f / la[2];

    const int q = q0 + wid * 16 + (lane >> 2);
    __half* op = g_o + ((size_t)b * SEQ + q) * DIM + h * HDIM;
    #pragma unroll
    for (int dt = 0; dt < 8; dt++) {
        int d = dt * 8 + 2 * (lane & 3);
        *(uint32_t*)(op + d)           = packh2(o[dt][0] * rlo, o[dt][1] * rlo);
        *(uint32_t*)(op + 8 * DIM + d) = packh2(o[dt][2] * rhi, o[dt][3] * rhi);
    }
}

// ---------------- launch ----------------
extern "C" void kernel_launch(void* const* d_in, const int* in_sizes, int n_in,
                              void* d_out, int out_size)
{
    const float* x     = (const float*)d_in[0];
    const float* ln_w  = (const float*)d_in[1];
    const float* ln_b  = (const float*)d_in[2];
    const float* qkv_w = (const float*)d_in[3];
    const float* qkv_b = (const float*)d_in[4];
    const float* out_w = (const float*)d_in[5];
    const float* out_b = (const float*)d_in[6];
    float* out = (float*)d_out;

    cudaFuncSetAttribute(gemm_tc<0>, cudaFuncAttributeMaxDynamicSharedMemorySize, GEMM_SMEM);
    cudaFuncSetAttribute(gemm_tc<1>, cudaFuncAttributeMaxDynamicSharedMemorySize, GEMM_SMEM);
    cudaFuncSetAttribute(attn_tc,    cudaFuncAttributeMaxDynamicSharedMemorySize, ATTN_SMEM);

    __half* wq; cudaGetSymbolAddress((void**)&wq, g_wq);
    __half* wo; cudaGetSymbolAddress((void**)&wo, g_wo);
    float* qb2; cudaGetSymbolAddress((void**)&qb2, g_qb2);

    ln_stats<<<NTOK, 256>>>(x);
    cvt_w<<<WQ_BLOCKS + WO_BLOCKS, 256>>>(qkv_w, out_w, ln_w);
    fold_bias<<<QKV_N / 256, 256>>>(qkv_w, qkv_b, ln_b);

    gemm_tc<0><<<dim3(QKV_N / 128, NTOK / 128), 256, GEMM_SMEM>>>(x, wq, qb2, nullptr, QKV_N, DIM);
    attn_tc<<<dim3(SEQ / 128, 32), 256, ATTN_SMEM>>>();
    gemm_tc<1><<<dim3(DIM / 128, NTOK / 128), 256, GEMM_SMEM>>>(nullptr, wo, out_b, out, DIM, DIM);
}

// round 11
// speedup vs baseline: 1.2730x; 1.2730x over previous
#include <cuda_runtime.h>
#include <cuda_fp16.h>
#include <math.h>
#include <cstdint>

#define DIM   512
#define NTOK  8192
#define HDIM  64
#define SEQ   2048
#define QKV_N 1536
// SCALE * log2(e): Q prescaled so softmax is a bare ex2
#define QS_LOG2E 0.18033688011112042f

// ---------------- scratch (fp16) ----------------
__device__ __align__(256) __half g_xn[NTOK * DIM];
__device__ __align__(256) __half g_q [NTOK * DIM];   // [bh][n][64], pre-scaled
__device__ __align__(256) __half g_k [NTOK * DIM];
__device__ __align__(256) __half g_v [NTOK * DIM];
__device__ __align__(256) __half g_o [NTOK * DIM];   // [t][512]
__device__ __align__(256) __half g_wq[QKV_N * DIM];
__device__ __align__(256) __half g_wo[DIM * DIM];

// ---------------- PTX helpers ----------------
__device__ __forceinline__ uint32_t smem_u32(const void* p) {
    uint32_t a;
    asm("{ .reg .u64 t; cvta.to.shared.u64 t, %1; cvt.u32.u64 %0, t; }" : "=r"(a) : "l"(p));
    return a;
}
#define CP_ASYNC16(dst, src) \
    asm volatile("cp.async.cg.shared.global [%0], [%1], 16;" :: "r"(dst), "l"(src))
#define CP_COMMIT() asm volatile("cp.async.commit_group;" ::: "memory")
#define CP_WAIT(n)  asm volatile("cp.async.wait_group %0;" :: "n"(n) : "memory")

__device__ __forceinline__ void ldsm4(uint32_t* r, uint32_t a) {
    asm volatile("ldmatrix.sync.aligned.m8n8.x4.shared.b16 {%0,%1,%2,%3}, [%4];"
                 : "=r"(r[0]), "=r"(r[1]), "=r"(r[2]), "=r"(r[3]) : "r"(a));
}
__device__ __forceinline__ void ldsm4t(uint32_t* r, uint32_t a) {
    asm volatile("ldmatrix.sync.aligned.m8n8.x4.trans.shared.b16 {%0,%1,%2,%3}, [%4];"
                 : "=r"(r[0]), "=r"(r[1]), "=r"(r[2]), "=r"(r[3]) : "r"(a));
}
__device__ __forceinline__ void mma16(float* d, const uint32_t* a, const uint32_t* b) {
    asm volatile(
        "mma.sync.aligned.m16n8k16.row.col.f32.f16.f16.f32 "
        "{%0,%1,%2,%3}, {%4,%5,%6,%7}, {%8,%9}, {%0,%1,%2,%3};"
        : "+f"(d[0]), "+f"(d[1]), "+f"(d[2]), "+f"(d[3])
        : "r"(a[0]), "r"(a[1]), "r"(a[2]), "r"(a[3]), "r"(b[0]), "r"(b[1]));
}
__device__ __forceinline__ uint32_t packh2(float lo, float hi) {
    __half2 h = __floats2half2_rn(lo, hi);
    return *reinterpret_cast<uint32_t*>(&h);
}
__device__ __forceinline__ float ex2(float x) {
    float r;
    asm("ex2.approx.f32 %0, %1;" : "=f"(r) : "f"(x));
    return r;
}
// 128B-row XOR swizzle on 16B units: conflict-free ldmatrix + cp.async
__device__ __forceinline__ uint32_t swz(uint32_t row, uint32_t c16) {
    return row * 128 + ((c16 ^ (row & 7)) * 16);
}

// ---------------- merged prep: LN (fp16 out) + both weight conversions -----
#define WQ_BLOCKS (QKV_N * DIM / 1024)     // 768
#define WO_BLOCKS (DIM * DIM / 1024)       // 256
#define PREP_BLOCKS (NTOK + WQ_BLOCKS + WO_BLOCKS)

__global__ __launch_bounds__(256) void prep_kernel(
    const float* __restrict__ x, const float* __restrict__ ln_w,
    const float* __restrict__ ln_b, const float* __restrict__ qkv_w,
    const float* __restrict__ out_w)
{
    int blk = blockIdx.x, t = threadIdx.x;
    if (blk < NTOK) {
        // LayerNorm row -> fp16 g_xn
        int row = blk;
        float2 v = ((const float2*)(x + (size_t)row * DIM))[t];
        float s = v.x + v.y, ss = v.x * v.x + v.y * v.y;
        #pragma unroll
        for (int off = 16; off > 0; off >>= 1) {
            s  += __shfl_xor_sync(0xffffffffu, s,  off);
            ss += __shfl_xor_sync(0xffffffffu, ss, off);
        }
        __shared__ float rs[8], rss[8];
        int wid = t >> 5, lane = t & 31;
        if (lane == 0) { rs[wid] = s; rss[wid] = ss; }
        __syncthreads();
        float S = 0.f, SS = 0.f;
        #pragma unroll
        for (int i = 0; i < 8; i++) { S += rs[i]; SS += rss[i]; }
        float mu = S * (1.0f / DIM);
        float var = SS * (1.0f / DIM) - mu * mu;
        float rinv = rsqrtf(var + 1e-5f);
        float2 wv = ((const float2*)ln_w)[t], bv = ((const float2*)ln_b)[t];
        ((uint32_t*)(g_xn + (size_t)row * DIM))[t] =
            packh2((v.x - mu) * rinv * wv.x + bv.x, (v.y - mu) * rinv * wv.y + bv.y);
    } else if (blk < NTOK + WQ_BLOCKS) {
        int i = (blk - NTOK) * 256 + t;
        float4 v = ((const float4*)qkv_w)[i];
        ((uint32_t*)g_wq)[i * 2 + 0] = packh2(v.x, v.y);
        ((uint32_t*)g_wq)[i * 2 + 1] = packh2(v.z, v.w);
    } else {
        int i = (blk - NTOK - WQ_BLOCKS) * 256 + t;
        float4 v = ((const float4*)out_w)[i];
        ((uint32_t*)g_wo)[i * 2 + 0] = packh2(v.x, v.y);
        ((uint32_t*)g_wo)[i * 2 + 1] = packh2(v.z, v.w);
    }
}

// ======== fp16 GEMM-NT (R8): 128x128 tile, 8 warps 64x32, BK=64 ===========
#define GEMM_SMEM (3 * 32768)

template <int MODE>
__global__ __launch_bounds__(256, 2) void gemm_tc(
    const __half* __restrict__ Bmat, const float* __restrict__ bias,
    float* __restrict__ Cout, int N, int K)
{
    extern __shared__ char smraw[];
    const uint32_t sb = smem_u32(smraw);
    const int tid = threadIdx.x, lane = tid & 31, wid = tid >> 5;
    const int wm = wid >> 2, wn = wid & 3;
    const int bm = blockIdx.y * 128, bn = blockIdx.x * 128;
    const __half* A = (MODE == 0) ? g_xn : g_o;

    const int lrow = tid >> 1, lc16 = (tid & 1) * 4;
    const __half* Ag = A    + (size_t)(bm + lrow) * K + lc16 * 8;
    const __half* Bg = Bmat + (size_t)(bn + lrow) * K + lc16 * 8;

    float acc[4][4][4];
    #pragma unroll
    for (int i = 0; i < 4; i++)
        #pragma unroll
        for (int j = 0; j < 4; j++)
            { acc[i][j][0]=0.f; acc[i][j][1]=0.f; acc[i][j][2]=0.f; acc[i][j][3]=0.f; }

    const int NC = K / 64;
    #pragma unroll
    for (int c = 0; c < 2; c++) {
        uint32_t base = sb + c * 32768;
        #pragma unroll
        for (int i = 0; i < 4; i++) {
            CP_ASYNC16(base + swz(lrow, lc16 + i),         (const char*)(Ag + c * 64 + i * 8));
            CP_ASYNC16(base + 16384 + swz(lrow, lc16 + i), (const char*)(Bg + c * 64 + i * 8));
        }
        CP_COMMIT();
    }

    const int arow = wm * 64 + (lane & 15);
    const int brow = wn * 32 + (lane & 7);
    const int acol = lane >> 4;
    const int bcol = lane >> 3;

    for (int c = 0; c < NC; c++) {
        if (c + 1 < NC) { CP_WAIT(1); } else { CP_WAIT(0); }
        __syncthreads();
        if (c + 2 < NC) {
            uint32_t base = sb + ((c + 2) % 3) * 32768;
            #pragma unroll
            for (int i = 0; i < 4; i++) {
                CP_ASYNC16(base + swz(lrow, lc16 + i),
                           (const char*)(Ag + (c + 2) * 64 + i * 8));
                CP_ASYNC16(base + 16384 + swz(lrow, lc16 + i),
                           (const char*)(Bg + (c + 2) * 64 + i * 8));
            }
            CP_COMMIT();
        }

        const uint32_t Ab = sb + (c % 3) * 32768;
        const uint32_t Bb = Ab + 16384;

        uint32_t afA[4][4], afB[4][4], bf[4][4];
        #pragma unroll
        for (int mt = 0; mt < 4; mt++)
            ldsm4(afA[mt], Ab + swz(arow + mt * 16, 0 + acol));
        #pragma unroll
        for (int nt = 0; nt < 4; nt++)
            ldsm4(bf[nt],  Bb + swz(brow + nt * 8,  0 + bcol));
        #pragma unroll
        for (int mt = 0; mt < 4; mt++)
            ldsm4(afB[mt], Ab + swz(arow + mt * 16, 2 + acol));

        #pragma unroll
        for (int mt = 0; mt < 4; mt++)
            #pragma unroll
            for (int nt = 0; nt < 4; nt++)
                mma16(acc[mt][nt], afA[mt], &bf[nt][0]);
        #pragma unroll
        for (int mt = 0; mt < 4; mt++)
            ldsm4(afA[mt], Ab + swz(arow + mt * 16, 4 + acol));
        #pragma unroll
        for (int mt = 0; mt < 4; mt++)
            #pragma unroll
            for (int nt = 0; nt < 4; nt++)
                mma16(acc[mt][nt], afB[mt], &bf[nt][2]);
        #pragma unroll
        for (int nt = 0; nt < 4; nt++)
            ldsm4(bf[nt],  Bb + swz(brow + nt * 8,  4 + bcol));
        #pragma unroll
        for (int mt = 0; mt < 4; mt++)
            ldsm4(afB[mt], Ab + swz(arow + mt * 16, 6 + acol));
        #pragma unroll
        for (int mt = 0; mt < 4; mt++)
            #pragma unroll
            for (int nt = 0; nt < 4; nt++)
                mma16(acc[mt][nt], afA[mt], &bf[nt][0]);
        #pragma unroll
        for (int mt = 0; mt < 4; mt++)
            #pragma unroll
            for (int nt = 0; nt < 4; nt++)
                mma16(acc[mt][nt], afB[mt], &bf[nt][2]);
    }

    // epilogue: hoist the 4 unique bias loads (n depends only on nt)
    float2 bbv[4];
    #pragma unroll
    for (int nt = 0; nt < 4; nt++)
        bbv[nt] = *(const float2*)(bias + bn + wn * 32 + nt * 8 + 2 * (lane & 3));

    #pragma unroll
    for (int mt = 0; mt < 4; mt++) {
        #pragma unroll
        for (int nt = 0; nt < 4; nt++) {
            int m = bm + wm * 64 + mt * 16 + (lane >> 2);
            int n = bn + wn * 32 + nt * 8 + 2 * (lane & 3);
            float lx = acc[mt][nt][0] + bbv[nt].x, ly = acc[mt][nt][1] + bbv[nt].y;
            float hx = acc[mt][nt][2] + bbv[nt].x, hy = acc[mt][nt][3] + bbv[nt].y;
            if (MODE == 0) {
                int which = n >> 9, h = (n >> 6) & 7, d = n & 63;
                if (which == 0) {    // pre-scale Q by SCALE*log2(e)
                    lx *= QS_LOG2E; ly *= QS_LOG2E; hx *= QS_LOG2E; hy *= QS_LOG2E;
                }
                __half* dstp = (which == 0) ? g_q : ((which == 1) ? g_k : g_v);
                int bidx = m >> 11, nn = m & 2047;
                size_t base = (size_t)((bidx << 3) + h) * SEQ;
                *(uint32_t*)&dstp[(base + nn)     * HDIM + d] = packh2(lx, ly);
                *(uint32_t*)&dstp[(base + nn + 8) * HDIM + d] = packh2(hx, hy);
            } else {
                *(float2*)&Cout[(size_t)m * N + n]       = make_float2(lx, ly);
                *(float2*)&Cout[(size_t)(m + 8) * N + n] = make_float2(hx, hy);
            }
        }
    }
}

// ======== Attention (byte-identical R8 win) ================================
#define ATTN_SMEM (16384 + 2 * 32768)

__global__ __launch_bounds__(256, 2) void attn_tc()
{
    extern __shared__ char smraw[];
    const uint32_t sb = smem_u32(smraw);
    const int tid = threadIdx.x, lane = tid & 31, wid = tid >> 5;
    const int bh = blockIdx.y, b = bh >> 3, h = bh & 7;
    const int q0 = blockIdx.x * 128;

    const __half* qg = g_q + (size_t)bh * SEQ * HDIM;
    const __half* kg = g_k + (size_t)bh * SEQ * HDIM;
    const __half* vg = g_v + (size_t)bh * SEQ * HDIM;

    const int lrow = tid >> 1, lc16 = (tid & 1) * 4;

    {
        const __half* src = qg + (size_t)(q0 + lrow) * HDIM + lc16 * 8;
        #pragma unroll
        for (int i = 0; i < 4; i++)
            CP_ASYNC16(sb + swz(lrow, lc16 + i), (const char*)(src + i * 8));
        CP_COMMIT();
        const __half* ks = kg + (size_t)lrow * HDIM + lc16 * 8;
        const __half* vs = vg + (size_t)lrow * HDIM + lc16 * 8;
        #pragma unroll
        for (int i = 0; i < 4; i++) {
            CP_ASYNC16(sb + 16384 + swz(lrow, lc16 + i), (const char*)(ks + i * 8));
            CP_ASYNC16(sb + 32768 + swz(lrow, lc16 + i), (const char*)(vs + i * 8));
        }
        CP_COMMIT();
    }

    CP_WAIT(1);
    __syncthreads();
    uint32_t qa[4][4];
    #pragma unroll
    for (int s = 0; s < 4; s++)
        ldsm4(qa[s], sb + swz(wid * 16 + (lane & 15), (s << 1) + (lane >> 4)));

    float o[8][4];
    #pragma unroll
    for (int i = 0; i < 8; i++)
        { o[i][0]=0.f; o[i][1]=0.f; o[i][2]=0.f; o[i][3]=0.f; }
    float la[4] = {0.f, 0.f, 0.f, 0.f};
    const uint32_t ones2[2] = {0x3C003C00u, 0x3C003C00u};

    const int krow7  = lane & 7;
    const int kcol   = lane >> 3;
    const int vrow15 = lane & 15;
    const int vcol   = lane >> 4;

    const int NT = SEQ / 128;
    for (int t = 0; t < NT; t++) {
        CP_WAIT(0);
        __syncthreads();
        if (t + 1 < NT) {
            uint32_t base = sb + 16384 + ((t + 1) & 1) * 32768;
            const __half* ks = kg + (size_t)((t + 1) * 128 + lrow) * HDIM + lc16 * 8;
            const __half* vs = vg + (size_t)((t + 1) * 128 + lrow) * HDIM + lc16 * 8;
            #pragma unroll
            for (int i = 0; i < 4; i++) {
                CP_ASYNC16(base + swz(lrow, lc16 + i),         (const char*)(ks + i * 8));
                CP_ASYNC16(base + 16384 + swz(lrow, lc16 + i), (const char*)(vs + i * 8));
            }
            CP_COMMIT();
        }

        const uint32_t Kb = sb + 16384 + (t & 1) * 32768;
        const uint32_t Vb = Kb + 16384;

        uint32_t kb[2][16];
        ldsm4(kb[0] + 0,  Kb + swz(krow7,     0 + kcol));
        ldsm4(kb[0] + 4,  Kb + swz(krow7,     4 + kcol));
        ldsm4(kb[0] + 8,  Kb + swz(8 + krow7, 0 + kcol));
        ldsm4(kb[0] + 12, Kb + swz(8 + krow7, 4 + kcol));

        #pragma unroll
        for (int g = 0; g < 8; g++) {
            const int kr = g * 16;
            uint32_t* cur = kb[g & 1];
            uint32_t vb[4][4];
            #pragma unroll
            for (int dtp = 0; dtp < 4; dtp++)
                ldsm4t(vb[dtp], Vb + swz(kr + vrow15, 2 * dtp + vcol));
            float sc0[4] = {0.f,0.f,0.f,0.f}, sc1[4] = {0.f,0.f,0.f,0.f};
            mma16(sc0, qa[0], cur + 0);  mma16(sc0, qa[1], cur + 2);
            mma16(sc0, qa[2], cur + 4);  mma16(sc0, qa[3], cur + 6);
            mma16(sc1, qa[0], cur + 8);  mma16(sc1, qa[1], cur + 10);
            mma16(sc1, qa[2], cur + 12); mma16(sc1, qa[3], cur + 14);
            if (g < 7) {
                uint32_t* nxt = kb[(g + 1) & 1];
                ldsm4(nxt + 0,  Kb + swz(kr + 16 + krow7, 0 + kcol));
                ldsm4(nxt + 4,  Kb + swz(kr + 16 + krow7, 4 + kcol));
                ldsm4(nxt + 8,  Kb + swz(kr + 24 + krow7, 0 + kcol));
                ldsm4(nxt + 12, Kb + swz(kr + 24 + krow7, 4 + kcol));
            }
            sc0[0] = ex2(sc0[0]); sc0[1] = ex2(sc0[1]);
            sc0[2] = ex2(sc0[2]); sc0[3] = ex2(sc0[3]);
            sc1[0] = ex2(sc1[0]); sc1[1] = ex2(sc1[1]);
            sc1[2] = ex2(sc1[2]); sc1[3] = ex2(sc1[3]);
            uint32_t pa[4];
            pa[0] = packh2(sc0[0], sc0[1]);
            pa[1] = packh2(sc0[2], sc0[3]);
            pa[2] = packh2(sc1[0], sc1[1]);
            pa[3] = packh2(sc1[2], sc1[3]);
            mma16(la, pa, ones2);
            #pragma unroll
            for (int dtp = 0; dtp < 4; dtp++) {
                mma16(o[2*dtp],     pa, vb[dtp]);
                mma16(o[2*dtp + 1], pa, vb[dtp] + 2);
            }
        }
    }

    float rlo = 1.0f / la[0], rhi = 1.0f / la[2];

    const int q = q0 + wid * 16 + (lane >> 2);
    __half* op = g_o + ((size_t)b * SEQ + q) * DIM + h * HDIM;
    #pragma unroll
    for (int dt = 0; dt < 8; dt++) {
        int d = dt * 8 + 2 * (lane & 3);
        *(uint32_t*)(op + d)           = packh2(o[dt][0] * rlo, o[dt][1] * rlo);
        *(uint32_t*)(op + 8 * DIM + d) = packh2(o[dt][2] * rhi, o[dt][3] * rhi);
    }
}

// ---------------- launch ----------------
extern "C" void kernel_launch(void* const* d_in, const int* in_sizes, int n_in,
                              void* d_out, int out_size)
{
    const float* x     = (const float*)d_in[0];
    const float* ln_w  = (const float*)d_in[1];
    const float* ln_b  = (const float*)d_in[2];
    const float* qkv_w = (const float*)d_in[3];
    const float* qkv_b = (const float*)d_in[4];
    const float* out_w = (const float*)d_in[5];
    const float* out_b = (const float*)d_in[6];
    float* out = (float*)d_out;

    cudaFuncSetAttribute(gemm_tc<0>, cudaFuncAttributeMaxDynamicSharedMemorySize, GEMM_SMEM);
    cudaFuncSetAttribute(gemm_tc<1>, cudaFuncAttributeMaxDynamicSharedMemorySize, GEMM_SMEM);
    cudaFuncSetAttribute(attn_tc,    cudaFuncAttributeMaxDynamicSharedMemorySize, ATTN_SMEM);

    __half* wq; cudaGetSymbolAddress((void**)&wq, g_wq);
    __half* wo; cudaGetSymbolAddress((void**)&wo, g_wo);

    // single merged prep launch: LN + both weight conversions
    prep_kernel<<<PREP_BLOCKS, 256>>>(x, ln_w, ln_b, qkv_w, out_w);

    gemm_tc<0><<<dim3(QKV_N / 128, NTOK / 128), 256, GEMM_SMEM>>>(wq, qkv_b, nullptr, QKV_N, DIM);
    attn_tc<<<dim3(SEQ / 128, 32), 256, ATTN_SMEM>>>();
    gemm_tc<1><<<dim3(DIM / 128, NTOK / 128), 256, GEMM_SMEM>>>(wo, out_b, out, DIM, DIM);
}